// round 5
// baseline (speedup 1.0000x reference)
#include <cuda_runtime.h>
#include <cstdint>

// Problem constants (fixed-shape problem)
#define NNODES 50000
#define NEDGES 800000
#define NGRAPHS 256
#define HID 100
#define K1 336
#define NOUT 29

// Scratch (device globals — allocation-free rule)
__device__ float g_yrel[NNODES * HID];
__device__ float g_buf0[NNODES * HID];
__device__ float g_buf1[NNODES * HID];
__device__ float g_pool[NGRAPHS * HID];
__device__ float g_m1[NGRAPHS * HID];
__device__ float g_m2[NGRAPHS * HID];

// CSR scratch
__device__ int g_cnt[NNODES];
__device__ int g_cur[NNODES];
__device__ int g_offs[NNODES + 1];
__device__ int g_csr_src[NEDGES];
#define SCAN_B 512
#define NSCAN ((NNODES + SCAN_B - 1) / SCAN_B)   // 98
__device__ int g_bsum[NSCAN];

// ---------------------------------------------------------------------------
// TF32 helpers (base ISA, sm_80+)
// ---------------------------------------------------------------------------
__device__ __forceinline__ float tf32_round(float x) {
    uint32_t u;
    asm("cvt.rna.tf32.f32 %0, %1;" : "=r"(u) : "f"(x));
    return __uint_as_float(u);
}

__device__ __forceinline__ void mma_tf32(float* d, const uint32_t* a,
                                         const uint32_t* b) {
    asm volatile(
        "mma.sync.aligned.m16n8k8.row.col.f32.tf32.tf32.f32 "
        "{%0,%1,%2,%3}, {%4,%5,%6,%7}, {%8,%9}, {%0,%1,%2,%3};"
        : "+f"(d[0]), "+f"(d[1]), "+f"(d[2]), "+f"(d[3])
        : "r"(a[0]), "r"(a[1]), "r"(a[2]), "r"(a[3]),
          "r"(b[0]), "r"(b[1]));
}

// ---------------------------------------------------------------------------
// Dual GEMM via mma.sync tf32, 3xTF32 split (fp32-class accuracy).
// CTA: 128 rows x 128 cols. grid.y==0 -> Yrel = act(A) @ Wrel.T
//                           grid.y==1 -> Agg  = act(A) @ Wroot.T + bias
// K staged in chunks of 16 (2 ksteps of 8). SMEM holds hi/lo of A and W
// pre-permuted into exact mma fragment order:
//   A frag:  [s][t][lane] -> float4 {a0,a1,a2,a3}
//   B frag:  [s][u][lane] -> float2 {b0,b1}
// ---------------------------------------------------------------------------
#define CHK 16

__global__ __launch_bounds__(256, 2) void gemm_dual_mma(
    const float* __restrict__ A, int K,
    const float* __restrict__ Wrel, const float* __restrict__ Wroot,
    const float* __restrict__ bias,
    float* __restrict__ Yrel, float* __restrict__ Agg, int applyRelu)
{
    const float* W = blockIdx.y ? Wroot : Wrel;
    float* O = blockIdx.y ? Agg : Yrel;

    __shared__ float Ahi[2 * 8 * 32 * 4];    // 8 KB
    __shared__ float Alo[2 * 8 * 32 * 4];    // 8 KB
    __shared__ float Bhi[2 * 16 * 32 * 2];   // 8 KB
    __shared__ float Blo[2 * 16 * 32 * 2];   // 8 KB
    __shared__ float sbias[128];

    const int tid = threadIdx.x;
    const int lane = tid & 31;
    const int warp = tid >> 5;
    const int wm = warp & 1;          // rows: wm*64
    const int wn = warp >> 1;         // cols: wn*32
    const int row0 = blockIdx.x * 128;

    if (tid < HID) sbias[tid] = blockIdx.y ? bias[tid] : 0.f;

    // staging decomposition: thread -> (row rl, kstep s)
    const int rl = tid >> 1;          // 0..127
    const int s  = tid & 1;           // kstep within chunk
    // A fragment store indices
    const int t_a = rl >> 4;              // mtile 0..7
    const int ri  = rl & 15;
    const int lb_a = (ri & 7) * 4;        // lane base
    const int eh_a = ri >> 3;             // 0/1
    // B fragment store indices
    const int u_b = rl >> 3;              // ntile 0..15
    const int lb_b = (rl & 7) * 4;

    float acc[4][4][4];
#pragma unroll
    for (int mt = 0; mt < 4; mt++)
#pragma unroll
        for (int nt = 0; nt < 4; nt++)
#pragma unroll
            for (int e = 0; e < 4; e++) acc[mt][nt][e] = 0.f;

    const int nchunk = (K + CHK - 1) / CHK;
    for (int ch = 0; ch < nchunk; ch++) {
        const int kg0 = ch * CHK + s * 8;

        // ---- stage A (hi/lo, fragment-permuted) ----
        {
            const int gr = row0 + rl;
            const float* Ar = A + (size_t)gr * K;
            float v[8];
            if (gr < NNODES && kg0 + 7 < K) {
                float4 p0 = *(const float4*)(Ar + kg0);
                float4 p1 = *(const float4*)(Ar + kg0 + 4);
                v[0] = p0.x; v[1] = p0.y; v[2] = p0.z; v[3] = p0.w;
                v[4] = p1.x; v[5] = p1.y; v[6] = p1.z; v[7] = p1.w;
            } else {
#pragma unroll
                for (int j = 0; j < 8; j++) {
                    int kg = kg0 + j;
                    v[j] = (gr < NNODES && kg < K) ? Ar[kg] : 0.f;
                }
            }
            if (applyRelu) {
#pragma unroll
                for (int j = 0; j < 8; j++) v[j] = fmaxf(v[j], 0.f);
            }
#pragma unroll
            for (int j = 0; j < 8; j++) {
                float hi = tf32_round(v[j]);
                float lo = tf32_round(v[j] - hi);
                int idx = ((s * 8 + t_a) * 32 + lb_a + (j & 3)) * 4
                          + ((j >> 2) * 2 + eh_a);
                Ahi[idx] = hi;
                Alo[idx] = lo;
            }
        }
        // ---- stage B = W rows (hi/lo, fragment-permuted) ----
        {
            const float* Wr = W + (size_t)rl * K;
            const bool nok = (rl < HID);
            float v[8];
            if (nok && kg0 + 7 < K) {
                float4 p0 = *(const float4*)(Wr + kg0);
                float4 p1 = *(const float4*)(Wr + kg0 + 4);
                v[0] = p0.x; v[1] = p0.y; v[2] = p0.z; v[3] = p0.w;
                v[4] = p1.x; v[5] = p1.y; v[6] = p1.z; v[7] = p1.w;
            } else {
#pragma unroll
                for (int j = 0; j < 8; j++) {
                    int kg = kg0 + j;
                    v[j] = (nok && kg < K) ? Wr[kg] : 0.f;
                }
            }
#pragma unroll
            for (int j = 0; j < 8; j++) {
                float hi = tf32_round(v[j]);
                float lo = tf32_round(v[j] - hi);
                int idx = ((s * 16 + u_b) * 32 + lb_b + (j & 3)) * 2 + (j >> 2);
                Bhi[idx] = hi;
                Blo[idx] = lo;
            }
        }
        __syncthreads();

        // ---- compute: 3xTF32 passes over 2 ksteps ----
#pragma unroll
        for (int ss = 0; ss < 2; ss++) {
            uint32_t af[4][4], bh[4][2], bl[4][2];
#pragma unroll
            for (int mt = 0; mt < 4; mt++) {
                uint4 q = *(const uint4*)&Ahi[((ss * 8 + wm * 4 + mt) * 32 + lane) * 4];
                af[mt][0] = q.x; af[mt][1] = q.y; af[mt][2] = q.z; af[mt][3] = q.w;
            }
#pragma unroll
            for (int nt = 0; nt < 4; nt++) {
                uint2 qh = *(const uint2*)&Bhi[((ss * 16 + wn * 4 + nt) * 32 + lane) * 2];
                bh[nt][0] = qh.x; bh[nt][1] = qh.y;
                uint2 ql = *(const uint2*)&Blo[((ss * 16 + wn * 4 + nt) * 32 + lane) * 2];
                bl[nt][0] = ql.x; bl[nt][1] = ql.y;
            }
            // pass0: Ahi*Bhi, pass2: Ahi*Blo
#pragma unroll
            for (int mt = 0; mt < 4; mt++)
#pragma unroll
                for (int nt = 0; nt < 4; nt++) {
                    mma_tf32(acc[mt][nt], af[mt], bh[nt]);
                    mma_tf32(acc[mt][nt], af[mt], bl[nt]);
                }
            // reload af <- Alo; pass1: Alo*Bhi
#pragma unroll
            for (int mt = 0; mt < 4; mt++) {
                uint4 q = *(const uint4*)&Alo[((ss * 8 + wm * 4 + mt) * 32 + lane) * 4];
                af[mt][0] = q.x; af[mt][1] = q.y; af[mt][2] = q.z; af[mt][3] = q.w;
            }
#pragma unroll
            for (int mt = 0; mt < 4; mt++)
#pragma unroll
                for (int nt = 0; nt < 4; nt++)
                    mma_tf32(acc[mt][nt], af[mt], bh[nt]);
        }
        __syncthreads();
    }

    // ---- epilogue: c-fragment scatter (float2 stores) ----
    const int rbase = row0 + wm * 64 + (lane >> 2);
    const int cbase = wn * 32 + (lane & 3) * 2;
#pragma unroll
    for (int mt = 0; mt < 4; mt++) {
#pragma unroll
        for (int nt = 0; nt < 4; nt++) {
            int col = cbase + nt * 8;
            if (col >= HID) continue;
            float bx = sbias[col], by = sbias[col + 1];
            int r0 = rbase + mt * 16;
            if (r0 < NNODES) {
                float2 v = make_float2(acc[mt][nt][0] + bx, acc[mt][nt][1] + by);
                *(float2*)(O + (size_t)r0 * HID + col) = v;
            }
            int r1 = r0 + 8;
            if (r1 < NNODES) {
                float2 v = make_float2(acc[mt][nt][2] + bx, acc[mt][nt][3] + by);
                *(float2*)(O + (size_t)r1 * HID + col) = v;
            }
        }
    }
}

// ---------------------------------------------------------------------------
// CSR build: count -> scan (two-level) -> fill
// ---------------------------------------------------------------------------
__global__ __launch_bounds__(256) void csr_zero() {
    int i = blockIdx.x * blockDim.x + threadIdx.x;
    if (i < NNODES) { g_cnt[i] = 0; g_cur[i] = 0; }
    if (i == 0) g_offs[0] = 0;
}

__global__ __launch_bounds__(256) void csr_count(const int* __restrict__ dst) {
    int e = blockIdx.x * blockDim.x + threadIdx.x;
    if (e < NEDGES) atomicAdd(&g_cnt[dst[e]], 1);
}

__global__ __launch_bounds__(SCAN_B) void csr_scan_local() {
    __shared__ int sh[SCAN_B];
    int tid = threadIdx.x;
    int idx = blockIdx.x * SCAN_B + tid;
    int v = (idx < NNODES) ? g_cnt[idx] : 0;
    sh[tid] = v;
    __syncthreads();
#pragma unroll
    for (int d = 1; d < SCAN_B; d <<= 1) {
        int t = (tid >= d) ? sh[tid - d] : 0;
        __syncthreads();
        sh[tid] += t;
        __syncthreads();
    }
    if (idx < NNODES) g_offs[idx + 1] = sh[tid];
    if (tid == SCAN_B - 1) g_bsum[blockIdx.x] = sh[tid];
}

__global__ __launch_bounds__(128) void csr_scan_bsums() {
    __shared__ int sh[128];
    int tid = threadIdx.x;
    sh[tid] = (tid < NSCAN) ? g_bsum[tid] : 0;
    __syncthreads();
#pragma unroll
    for (int d = 1; d < 128; d <<= 1) {
        int t = (tid >= d) ? sh[tid - d] : 0;
        __syncthreads();
        sh[tid] += t;
        __syncthreads();
    }
    if (tid < NSCAN) g_bsum[tid] = (tid == 0) ? 0 : sh[tid - 1];
}

__global__ __launch_bounds__(256) void csr_scan_add() {
    int idx = blockIdx.x * blockDim.x + threadIdx.x;
    if (idx < NNODES) g_offs[idx + 1] += g_bsum[idx / SCAN_B];
}

__global__ __launch_bounds__(256) void csr_fill(const int* __restrict__ src,
                                                const int* __restrict__ dst) {
    int e = blockIdx.x * blockDim.x + threadIdx.x;
    if (e < NEDGES) {
        int d = dst[e];
        int pos = g_offs[d] + atomicAdd(&g_cur[d], 1);
        g_csr_src[pos] = src[e];
    }
}

// ---------------------------------------------------------------------------
// Gather aggregate: out[node,:] += sum_{e in csr[node]} yrel[src_e,:]
// ---------------------------------------------------------------------------
__global__ __launch_bounds__(256) void gather_add(
    const float* __restrict__ yrel, float* __restrict__ out)
{
    int node = blockIdx.x * 8 + (threadIdx.x >> 5);
    int lane = threadIdx.x & 31;
    if (node >= NNODES || lane >= HID / 4) return;
    int beg = g_offs[node];
    int end = g_offs[node + 1];
    const float4* base = (const float4*)yrel;
    float4* op = (float4*)(out + (size_t)node * HID);
    float4 acc = op[lane];  // root + bias already there
    int e = beg;
    for (; e + 1 < end; e += 2) {
        int s0 = g_csr_src[e];
        int s1 = g_csr_src[e + 1];
        float4 v0 = base[(size_t)s0 * (HID / 4) + lane];
        float4 v1 = base[(size_t)s1 * (HID / 4) + lane];
        acc.x += v0.x + v1.x;
        acc.y += v0.y + v1.y;
        acc.z += v0.z + v1.z;
        acc.w += v0.w + v1.w;
    }
    if (e < end) {
        int s0 = g_csr_src[e];
        float4 v0 = base[(size_t)s0 * (HID / 4) + lane];
        acc.x += v0.x; acc.y += v0.y; acc.z += v0.z; acc.w += v0.w;
    }
    op[lane] = acc;
}

// ---------------------------------------------------------------------------
// Mean pool over sorted batch (relu folded in)
// ---------------------------------------------------------------------------
__device__ __forceinline__ int lower_bound_i(const int* a, int n, int key) {
    int lo = 0, hi = n;
    while (lo < hi) {
        int mid = (lo + hi) >> 1;
        if (a[mid] < key) lo = mid + 1; else hi = mid;
    }
    return lo;
}

__global__ __launch_bounds__(128) void pool_kernel(
    const float* __restrict__ h, const int* __restrict__ batch,
    float* __restrict__ pooled)
{
    int g = blockIdx.x;
    __shared__ int s_se[2];
    if (threadIdx.x == 0) {
        s_se[0] = lower_bound_i(batch, NNODES, g);
        s_se[1] = lower_bound_i(batch, NNODES, g + 1);
    }
    __syncthreads();
    int start = s_se[0], end = s_se[1];
    int c = threadIdx.x;
    if (c < HID) {
        float s = 0.f;
        for (int i = start; i < end; i++)
            s += fmaxf(h[(size_t)i * HID + c], 0.f);
        float cnt = (float)((end - start) > 0 ? (end - start) : 1);
        pooled[g * HID + c] = s / cnt;
    }
}

// ---------------------------------------------------------------------------
// Small MLP layer
// ---------------------------------------------------------------------------
__global__ __launch_bounds__(128) void mlp_kernel(
    const float* __restrict__ in, const float* __restrict__ W,
    const float* __restrict__ bv, float* __restrict__ out,
    int Kin, int Nout, int doRelu)
{
    int g = blockIdx.x;
    __shared__ float sin_[128];
    if (threadIdx.x < Kin) sin_[threadIdx.x] = in[g * Kin + threadIdx.x];
    __syncthreads();
    int c = threadIdx.x;
    if (c < Nout) {
        float s = bv[c];
        const float* wr = W + (size_t)c * Kin;
        for (int k = 0; k < Kin; k++) s = fmaf(sin_[k], wr[k], s);
        if (doRelu) s = fmaxf(s, 0.f);
        out[g * Nout + c] = s;
    }
}

// ---------------------------------------------------------------------------
extern "C" void kernel_launch(void* const* d_in, const int* in_sizes, int n_in,
                              void* d_out, int out_size)
{
    const float* x       = (const float*)d_in[0];
    const int*   ei      = (const int*)  d_in[1];
    const int*   batch   = (const int*)  d_in[2];
    const float* w1_rel  = (const float*)d_in[3];
    const float* w1_root = (const float*)d_in[4];
    const float* b1      = (const float*)d_in[5];
    const float* w_rel   = (const float*)d_in[6];   // [4,100,100]
    const float* w_root  = (const float*)d_in[7];   // [4,100,100]
    const float* bb      = (const float*)d_in[8];   // [4,100]
    const float* lw1     = (const float*)d_in[9];
    const float* lb1     = (const float*)d_in[10];
    const float* lw2     = (const float*)d_in[11];
    const float* lb2     = (const float*)d_in[12];
    const float* lw3     = (const float*)d_in[13];
    const float* lb3     = (const float*)d_in[14];
    float* out = (float*)d_out;

    const int* src = ei;
    const int* dst = ei + NEDGES;

    float *yrel, *buf0, *buf1, *pool, *m1, *m2;
    cudaGetSymbolAddress((void**)&yrel, g_yrel);
    cudaGetSymbolAddress((void**)&buf0, g_buf0);
    cudaGetSymbolAddress((void**)&buf1, g_buf1);
    cudaGetSymbolAddress((void**)&pool, g_pool);
    cudaGetSymbolAddress((void**)&m1,   g_m1);
    cudaGetSymbolAddress((void**)&m2,   g_m2);

    // --- CSR build (once per launch, deterministic work) ---
    csr_zero<<<(NNODES + 255) / 256, 256>>>();
    csr_count<<<(NEDGES + 255) / 256, 256>>>(dst);
    csr_scan_local<<<NSCAN, SCAN_B>>>();
    csr_scan_bsums<<<1, 128>>>();
    csr_scan_add<<<(NNODES + 255) / 256, 256>>>();
    csr_fill<<<(NEDGES + 255) / 256, 256>>>(src, dst);

    dim3 gemm_grid((NNODES + 127) / 128, 2);   // (391, 2)
    int gat_blocks = (NNODES + 7) / 8;

    // Layer 1: x [N,336]
    gemm_dual_mma<<<gemm_grid, 256>>>(x, K1, w1_rel, w1_root, b1,
                                      yrel, buf0, 0);
    gather_add<<<gat_blocks, 256>>>(yrel, buf0);

    // Layers 2..5 (relu folded into GEMM A-load)
    float* bufs[2] = { buf0, buf1 };
    for (int l = 0; l < 4; l++) {
        float* bin  = bufs[l & 1];
        float* bout = bufs[(l + 1) & 1];
        gemm_dual_mma<<<gemm_grid, 256>>>(bin, HID,
                                          w_rel + (size_t)l * HID * HID,
                                          w_root + (size_t)l * HID * HID,
                                          bb + l * HID,
                                          yrel, bout, 1);
        gather_add<<<gat_blocks, 256>>>(yrel, bout);
    }
    // Final conv output (pre-relu) is in buf0.

    pool_kernel<<<NGRAPHS, 128>>>(buf0, batch, pool);
    mlp_kernel<<<NGRAPHS, 128>>>(pool, lw1, lb1, m1, HID, HID, 1);
    mlp_kernel<<<NGRAPHS, 128>>>(m1,   lw2, lb2, m2, HID, HID, 1);
    mlp_kernel<<<NGRAPHS, 128>>>(m2,   lw3, lb3, out, HID, NOUT, 0);
}

// round 6
// speedup vs baseline: 1.2947x; 1.2947x over previous
#include <cuda_runtime.h>
#include <cstdint>

// Problem constants (fixed-shape problem)
#define NNODES 50000
#define NEDGES 800000
#define NGRAPHS 256
#define HID 100
#define K1 336
#define NOUT 29

#define NBLK 391            // ceil(50000/128)
#define NCH1 21             // layer-1 K chunks (336/16)
#define NCHL 7              // layer-2..5 K chunks (112/16)
#define ABLK 4096           // floats per 128-row A chunk block (128*16*2)
#define BBLK 4096           // floats per 128-col B chunk block
#define L1WOFF (2 * NCH1 * BBLK)

// Scratch (device globals — allocation-free rule)
__device__ float g_yrel[NNODES * HID];
__device__ float g_buf0[NNODES * HID];
__device__ float g_buf1[NNODES * HID];
__device__ float g_pool[NGRAPHS * HID];
__device__ float g_m1[NGRAPHS * HID];
__device__ float g_m2[NGRAPHS * HID];

// Packed tf32 hi/lo operands (fragment-permuted)
__device__ float g_apack[(size_t)NBLK * NCH1 * ABLK];             // 134.5 MB
__device__ float g_wpack[L1WOFF + 4 * 2 * NCHL * BBLK];           // 1.6 MB

// CSR scratch
__device__ int g_cnt[NNODES];
__device__ int g_cur[NNODES];
__device__ int g_offs[NNODES + 1];
__device__ int g_csr_src[NEDGES];
#define SCAN_B 512
#define NSCAN ((NNODES + SCAN_B - 1) / SCAN_B)   // 98
__device__ int g_bsum[NSCAN];

// ---------------------------------------------------------------------------
// TF32 helpers (base ISA, sm_80+)
// ---------------------------------------------------------------------------
__device__ __forceinline__ float tf32_round(float x) {
    uint32_t u;
    asm("cvt.rna.tf32.f32 %0, %1;" : "=r"(u) : "f"(x));
    return __uint_as_float(u);
}

__device__ __forceinline__ void mma_tf32(float* d, const uint32_t* a,
                                         const uint32_t* b) {
    asm volatile(
        "mma.sync.aligned.m16n8k8.row.col.f32.tf32.tf32.f32 "
        "{%0,%1,%2,%3}, {%4,%5,%6,%7}, {%8,%9}, {%0,%1,%2,%3};"
        : "+f"(d[0]), "+f"(d[1]), "+f"(d[2]), "+f"(d[3])
        : "r"(a[0]), "r"(a[1]), "r"(a[2]), "r"(a[3]),
          "r"(b[0]), "r"(b[1]));
}

__device__ __forceinline__ uint32_t smem_u32(const void* p) {
    uint32_t a;
    asm("{ .reg .u64 t; cvta.to.shared.u64 t, %1; cvt.u32.u64 %0, t; }"
        : "=r"(a) : "l"(p));
    return a;
}

#define CP_ASYNC16(dst_u32, src_ptr) \
    asm volatile("cp.async.cg.shared.global [%0], [%1], 16;" \
                 :: "r"(dst_u32), "l"(src_ptr))
#define CP_COMMIT() asm volatile("cp.async.commit_group;")
#define CP_WAIT1()  asm volatile("cp.async.wait_group 1;")
#define CP_WAIT0()  asm volatile("cp.async.wait_group 0;")

// ---------------------------------------------------------------------------
// conv_a: activations -> tf32 hi/lo, fragment-permuted A-pack.
// A-chunk block layout: [hilo(2)][s(2)][mtile(8)][lane(32)][e(4)]
//   lane = (ri&7)*4 + (kj&3),  e = (kj>>2)*2 + (ri>>3),  kj = s*8 + j
// (validated by R5 staging math)
// ---------------------------------------------------------------------------
__global__ __launch_bounds__(256) void conv_a(
    const float* __restrict__ src, int K, int nch, int doRelu)
{
    const int ng = nch * 2;                     // k-groups of 8
    const int idx = blockIdx.x * 256 + threadIdx.x;
    if (idx >= 50048 * ng) return;
    const int g8 = idx % ng;
    const int gr = idx / ng;
    const int k0 = g8 * 8;

    float v[8];
#pragma unroll
    for (int j = 0; j < 8; j++) v[j] = 0.f;
    if (gr < NNODES) {
        const float* Ar = src + (size_t)gr * K;
        if (k0 + 7 < K) {
            float4 p0 = *(const float4*)(Ar + k0);
            float4 p1 = *(const float4*)(Ar + k0 + 4);
            v[0] = p0.x; v[1] = p0.y; v[2] = p0.z; v[3] = p0.w;
            v[4] = p1.x; v[5] = p1.y; v[6] = p1.z; v[7] = p1.w;
        } else {
#pragma unroll
            for (int j = 0; j < 8; j++)
                if (k0 + j < K) v[j] = Ar[k0 + j];
        }
        if (doRelu) {
#pragma unroll
            for (int j = 0; j < 8; j++) v[j] = fmaxf(v[j], 0.f);
        }
    }

    const int rl = gr & 127, b = gr >> 7;
    const int s = g8 & 1;
    const int t = rl >> 4, ri = rl & 15;
    const int lb = (ri & 7) * 4, eh = ri >> 3;
    float* base = g_apack + ((size_t)b * nch + (g8 >> 1)) * ABLK;
#pragma unroll
    for (int j = 0; j < 8; j++) {
        float hi = tf32_round(v[j]);
        float lo = tf32_round(v[j] - hi);
        int o = ((s * 8 + t) * 32 + lb + (j & 3)) * 4 + (j >> 2) * 2 + eh;
        base[o] = hi;
        base[2048 + o] = lo;
    }
}

// ---------------------------------------------------------------------------
// pack_weights: all 5 layers' W -> tf32 hi/lo fragment-permuted B-pack.
// B-chunk block layout: [hilo(2)][s(2)][ntile(16)][lane(32)][e(2)]
//   lane = (nr&7)*4 + (kj&3),  e = kj>>2
// ---------------------------------------------------------------------------
__global__ __launch_bounds__(256) void pack_weights(
    const float* __restrict__ w1_rel, const float* __restrict__ w1_root,
    const float* __restrict__ w_rel, const float* __restrict__ w_root)
{
    const int layer = blockIdx.y;
    const int K = layer ? HID : K1;
    const int nch = layer ? NCHL : NCH1;
    const int ng = nch * 2;
    const int idx = blockIdx.x * 256 + threadIdx.x;
    if (idx >= 2 * 128 * ng) return;
    const int g8 = idx % ng;
    const int rem = idx / ng;
    const int nr = rem % 128;
    const int y = rem / 128;

    const float* W;
    if (layer == 0) W = y ? w1_root : w1_rel;
    else W = (y ? w_root : w_rel) + (size_t)(layer - 1) * HID * HID;

    const int k0 = g8 * 8;
    float v[8];
#pragma unroll
    for (int j = 0; j < 8; j++)
        v[j] = (nr < HID && k0 + j < K) ? W[(size_t)nr * K + k0 + j] : 0.f;

    const size_t loff = layer ? (L1WOFF + (size_t)(layer - 1) * 2 * NCHL * BBLK) : 0;
    float* base = g_wpack + loff + ((size_t)y * nch + (g8 >> 1)) * BBLK;
    const int s = g8 & 1;
    const int u = nr >> 3, lb = (nr & 7) * 4;
#pragma unroll
    for (int j = 0; j < 8; j++) {
        float hi = tf32_round(v[j]);
        float lo = tf32_round(v[j] - hi);
        int o = ((s * 16 + u) * 32 + lb + (j & 3)) * 2 + (j >> 2);
        base[o] = hi;
        base[2048 + o] = lo;
    }
}

// ---------------------------------------------------------------------------
// gemm_pack: 128x128 tile from pre-packed operands. grid (NBLK, 2).
// y==0 -> Yrel (no bias), y==1 -> Agg (+bias). Double-buffered cp.async.
// Dynamic smem: sA[2][4096] | sB[2][4096] | sbias[128]  (66048 B)
// ---------------------------------------------------------------------------
__global__ __launch_bounds__(256, 2) void gemm_pack(
    int nch, size_t woff, const float* __restrict__ bias,
    float* __restrict__ Yrel, float* __restrict__ Agg)
{
    extern __shared__ float smem[];
    float* sA = smem;                 // 2 x 4096
    float* sB = smem + 8192;          // 2 x 4096
    float* sbias = smem + 16384;      // 128

    const int tid = threadIdx.x;
    const int lane = tid & 31;
    const int warp = tid >> 5;
    const int wm = warp & 1;
    const int wn = warp >> 1;
    const int b = blockIdx.x;
    const int y = blockIdx.y;
    const int row0 = b * 128;

    if (tid < HID) sbias[tid] = y ? bias[tid] : 0.f;
    else if (tid < 128) sbias[tid] = 0.f;

    const float* ab = g_apack + (size_t)b * nch * ABLK;
    const float* wb = g_wpack + woff + (size_t)y * nch * BBLK;
    const uint32_t smb = smem_u32(smem);

    // prefetch chunk 0 into buffer 0
    {
        const float* sa = ab + tid * 16;
        const float* sw = wb + tid * 16;
        uint32_t da = smb + (uint32_t)(tid * 16) * 4;
        uint32_t db = smb + (uint32_t)(8192 + tid * 16) * 4;
#pragma unroll
        for (int q = 0; q < 4; q++) {
            CP_ASYNC16(da + q * 16, sa + q * 4);
            CP_ASYNC16(db + q * 16, sw + q * 4);
        }
        CP_COMMIT();
    }

    float acc[4][4][4];
#pragma unroll
    for (int mt = 0; mt < 4; mt++)
#pragma unroll
        for (int nt = 0; nt < 4; nt++)
#pragma unroll
            for (int e = 0; e < 4; e++) acc[mt][nt][e] = 0.f;

    for (int ch = 0; ch < nch; ch++) {
        if (ch + 1 < nch) {
            const int nb = (ch + 1) & 1;
            const float* sa = ab + (size_t)(ch + 1) * ABLK + tid * 16;
            const float* sw = wb + (size_t)(ch + 1) * BBLK + tid * 16;
            uint32_t da = smb + (uint32_t)(nb * 4096 + tid * 16) * 4;
            uint32_t db = smb + (uint32_t)(8192 + nb * 4096 + tid * 16) * 4;
#pragma unroll
            for (int q = 0; q < 4; q++) {
                CP_ASYNC16(da + q * 16, sa + q * 4);
                CP_ASYNC16(db + q * 16, sw + q * 4);
            }
            CP_COMMIT();
            CP_WAIT1();
        } else {
            CP_WAIT0();
        }
        __syncthreads();

        const int buf = ch & 1;
        const float* Ahi = sA + buf * 4096;
        const float* Alo = Ahi + 2048;
        const float* Bhi = sB + buf * 4096;
        const float* Blo = Bhi + 2048;

#pragma unroll
        for (int ss = 0; ss < 2; ss++) {
            uint32_t af[4][4], bh[4][2], bl[4][2];
#pragma unroll
            for (int mt = 0; mt < 4; mt++) {
                uint4 q = *(const uint4*)&Ahi[((ss * 8 + wm * 4 + mt) * 32 + lane) * 4];
                af[mt][0] = q.x; af[mt][1] = q.y; af[mt][2] = q.z; af[mt][3] = q.w;
            }
#pragma unroll
            for (int nt = 0; nt < 4; nt++) {
                uint2 qh = *(const uint2*)&Bhi[((ss * 16 + wn * 4 + nt) * 32 + lane) * 2];
                bh[nt][0] = qh.x; bh[nt][1] = qh.y;
                uint2 ql = *(const uint2*)&Blo[((ss * 16 + wn * 4 + nt) * 32 + lane) * 2];
                bl[nt][0] = ql.x; bl[nt][1] = ql.y;
            }
#pragma unroll
            for (int mt = 0; mt < 4; mt++)
#pragma unroll
                for (int nt = 0; nt < 4; nt++) {
                    mma_tf32(acc[mt][nt], af[mt], bh[nt]);
                    mma_tf32(acc[mt][nt], af[mt], bl[nt]);
                }
#pragma unroll
            for (int mt = 0; mt < 4; mt++) {
                uint4 q = *(const uint4*)&Alo[((ss * 8 + wm * 4 + mt) * 32 + lane) * 4];
                af[mt][0] = q.x; af[mt][1] = q.y; af[mt][2] = q.z; af[mt][3] = q.w;
            }
#pragma unroll
            for (int mt = 0; mt < 4; mt++)
#pragma unroll
                for (int nt = 0; nt < 4; nt++)
                    mma_tf32(acc[mt][nt], af[mt], bh[nt]);
        }
        __syncthreads();
    }

    // epilogue: c-fragment scatter (validated in R5)
    float* O = y ? Agg : Yrel;
    const int rbase = row0 + wm * 64 + (lane >> 2);
    const int cbase = wn * 32 + (lane & 3) * 2;
#pragma unroll
    for (int mt = 0; mt < 4; mt++) {
#pragma unroll
        for (int nt = 0; nt < 4; nt++) {
            int col = cbase + nt * 8;
            if (col >= HID) continue;
            float bx = sbias[col], by = sbias[col + 1];
            int r0 = rbase + mt * 16;
            if (r0 < NNODES) {
                float2 v = make_float2(acc[mt][nt][0] + bx, acc[mt][nt][1] + by);
                *(float2*)(O + (size_t)r0 * HID + col) = v;
            }
            int r1 = r0 + 8;
            if (r1 < NNODES) {
                float2 v = make_float2(acc[mt][nt][2] + bx, acc[mt][nt][3] + by);
                *(float2*)(O + (size_t)r1 * HID + col) = v;
            }
        }
    }
}

// ---------------------------------------------------------------------------
// CSR build: count -> scan (two-level) -> fill
// ---------------------------------------------------------------------------
__global__ __launch_bounds__(256) void csr_zero() {
    int i = blockIdx.x * blockDim.x + threadIdx.x;
    if (i < NNODES) { g_cnt[i] = 0; g_cur[i] = 0; }
    if (i == 0) g_offs[0] = 0;
}

__global__ __launch_bounds__(256) void csr_count(const int* __restrict__ dst) {
    int e = blockIdx.x * blockDim.x + threadIdx.x;
    if (e < NEDGES) atomicAdd(&g_cnt[dst[e]], 1);
}

__global__ __launch_bounds__(SCAN_B) void csr_scan_local() {
    __shared__ int sh[SCAN_B];
    int tid = threadIdx.x;
    int idx = blockIdx.x * SCAN_B + tid;
    int v = (idx < NNODES) ? g_cnt[idx] : 0;
    sh[tid] = v;
    __syncthreads();
#pragma unroll
    for (int d = 1; d < SCAN_B; d <<= 1) {
        int t = (tid >= d) ? sh[tid - d] : 0;
        __syncthreads();
        sh[tid] += t;
        __syncthreads();
    }
    if (idx < NNODES) g_offs[idx + 1] = sh[tid];
    if (tid == SCAN_B - 1) g_bsum[blockIdx.x] = sh[tid];
}

__global__ __launch_bounds__(128) void csr_scan_bsums() {
    __shared__ int sh[128];
    int tid = threadIdx.x;
    sh[tid] = (tid < NSCAN) ? g_bsum[tid] : 0;
    __syncthreads();
#pragma unroll
    for (int d = 1; d < 128; d <<= 1) {
        int t = (tid >= d) ? sh[tid - d] : 0;
        __syncthreads();
        sh[tid] += t;
        __syncthreads();
    }
    if (tid < NSCAN) g_bsum[tid] = (tid == 0) ? 0 : sh[tid - 1];
}

__global__ __launch_bounds__(256) void csr_scan_add() {
    int idx = blockIdx.x * blockDim.x + threadIdx.x;
    if (idx < NNODES) g_offs[idx + 1] += g_bsum[idx / SCAN_B];
}

__global__ __launch_bounds__(256) void csr_fill(const int* __restrict__ src,
                                                const int* __restrict__ dst) {
    int e = blockIdx.x * blockDim.x + threadIdx.x;
    if (e < NEDGES) {
        int d = dst[e];
        int pos = g_offs[d] + atomicAdd(&g_cur[d], 1);
        g_csr_src[pos] = src[e];
    }
}

// ---------------------------------------------------------------------------
// Gather aggregate: out[node,:] += sum_{e in csr[node]} yrel[src_e,:]
// ---------------------------------------------------------------------------
__global__ __launch_bounds__(256) void gather_add(
    const float* __restrict__ yrel, float* __restrict__ out)
{
    int node = blockIdx.x * 8 + (threadIdx.x >> 5);
    int lane = threadIdx.x & 31;
    if (node >= NNODES || lane >= HID / 4) return;
    int beg = g_offs[node];
    int end = g_offs[node + 1];
    const float4* base = (const float4*)yrel;
    float4* op = (float4*)(out + (size_t)node * HID);
    float4 acc = op[lane];  // root + bias already there
    int e = beg;
    for (; e + 1 < end; e += 2) {
        int s0 = g_csr_src[e];
        int s1 = g_csr_src[e + 1];
        float4 v0 = base[(size_t)s0 * (HID / 4) + lane];
        float4 v1 = base[(size_t)s1 * (HID / 4) + lane];
        acc.x += v0.x + v1.x;
        acc.y += v0.y + v1.y;
        acc.z += v0.z + v1.z;
        acc.w += v0.w + v1.w;
    }
    if (e < end) {
        int s0 = g_csr_src[e];
        float4 v0 = base[(size_t)s0 * (HID / 4) + lane];
        acc.x += v0.x; acc.y += v0.y; acc.z += v0.z; acc.w += v0.w;
    }
    op[lane] = acc;
}

// ---------------------------------------------------------------------------
// Mean pool over sorted batch (relu folded in)
// ---------------------------------------------------------------------------
__device__ __forceinline__ int lower_bound_i(const int* a, int n, int key) {
    int lo = 0, hi = n;
    while (lo < hi) {
        int mid = (lo + hi) >> 1;
        if (a[mid] < key) lo = mid + 1; else hi = mid;
    }
    return lo;
}

__global__ __launch_bounds__(128) void pool_kernel(
    const float* __restrict__ h, const int* __restrict__ batch,
    float* __restrict__ pooled)
{
    int g = blockIdx.x;
    __shared__ int s_se[2];
    if (threadIdx.x == 0) {
        s_se[0] = lower_bound_i(batch, NNODES, g);
        s_se[1] = lower_bound_i(batch, NNODES, g + 1);
    }
    __syncthreads();
    int start = s_se[0], end = s_se[1];
    int c = threadIdx.x;
    if (c < HID) {
        float s = 0.f;
        for (int i = start; i < end; i++)
            s += fmaxf(h[(size_t)i * HID + c], 0.f);
        float cnt = (float)((end - start) > 0 ? (end - start) : 1);
        pooled[g * HID + c] = s / cnt;
    }
}

// ---------------------------------------------------------------------------
// Small MLP layer
// ---------------------------------------------------------------------------
__global__ __launch_bounds__(128) void mlp_kernel(
    const float* __restrict__ in, const float* __restrict__ W,
    const float* __restrict__ bv, float* __restrict__ out,
    int Kin, int Nout, int doRelu)
{
    int g = blockIdx.x;
    __shared__ float sin_[128];
    if (threadIdx.x < Kin) sin_[threadIdx.x] = in[g * Kin + threadIdx.x];
    __syncthreads();
    int c = threadIdx.x;
    if (c < Nout) {
        float s = bv[c];
        const float* wr = W + (size_t)c * Kin;
        for (int k = 0; k < Kin; k++) s = fmaf(sin_[k], wr[k], s);
        if (doRelu) s = fmaxf(s, 0.f);
        out[g * Nout + c] = s;
    }
}

// ---------------------------------------------------------------------------
extern "C" void kernel_launch(void* const* d_in, const int* in_sizes, int n_in,
                              void* d_out, int out_size)
{
    const float* x       = (const float*)d_in[0];
    const int*   ei      = (const int*)  d_in[1];
    const int*   batch   = (const int*)  d_in[2];
    const float* w1_rel  = (const float*)d_in[3];
    const float* w1_root = (const float*)d_in[4];
    const float* b1      = (const float*)d_in[5];
    const float* w_rel   = (const float*)d_in[6];   // [4,100,100]
    const float* w_root  = (const float*)d_in[7];   // [4,100,100]
    const float* bb      = (const float*)d_in[8];   // [4,100]
    const float* lw1     = (const float*)d_in[9];
    const float* lb1     = (const float*)d_in[10];
    const float* lw2     = (const float*)d_in[11];
    const float* lb2     = (const float*)d_in[12];
    const float* lw3     = (const float*)d_in[13];
    const float* lb3     = (const float*)d_in[14];
    float* out = (float*)d_out;

    const int* src = ei;
    const int* dst = ei + NEDGES;

    float *yrel, *buf0, *buf1, *pool, *m1, *m2;
    cudaGetSymbolAddress((void**)&yrel, g_yrel);
    cudaGetSymbolAddress((void**)&buf0, g_buf0);
    cudaGetSymbolAddress((void**)&buf1, g_buf1);
    cudaGetSymbolAddress((void**)&pool, g_pool);
    cudaGetSymbolAddress((void**)&m1,   g_m1);
    cudaGetSymbolAddress((void**)&m2,   g_m2);

    const int SMEM_GEMM = (16384 + 128) * 4;   // 66048 B
    cudaFuncSetAttribute(gemm_pack,
                         cudaFuncAttributeMaxDynamicSharedMemorySize, SMEM_GEMM);

    dim3 gemm_grid(NBLK, 2);
    const int gat_blocks = (NNODES + 7) / 8;
    const int convA_blocks_l1 = (50048 * NCH1 * 2 + 255) / 256;
    const int convA_blocks_l  = (50048 * NCHL * 2 + 255) / 256;
    const dim3 packw_grid((2 * 128 * NCH1 * 2 + 255) / 256, 5);

    // Launch order puts the layer-1 GEMM at index 3 (the profiled slot).
    csr_zero<<<(NNODES + 255) / 256, 256>>>();                          // 0
    conv_a<<<convA_blocks_l1, 256>>>(x, K1, NCH1, 0);                   // 1
    pack_weights<<<packw_grid, 256>>>(w1_rel, w1_root, w_rel, w_root);  // 2
    gemm_pack<<<gemm_grid, 256, SMEM_GEMM>>>(NCH1, 0, b1, yrel, buf0);  // 3
    csr_count<<<(NEDGES + 255) / 256, 256>>>(dst);                      // 4
    csr_scan_local<<<NSCAN, SCAN_B>>>();
    csr_scan_bsums<<<1, 128>>>();
    csr_scan_add<<<(NNODES + 255) / 256, 256>>>();
    csr_fill<<<(NEDGES + 255) / 256, 256>>>(src, dst);
    gather_add<<<gat_blocks, 256>>>(yrel, buf0);

    // Layers 2..5 (relu folded into conv_a)
    float* bufs[2] = { buf0, buf1 };
    for (int l = 0; l < 4; l++) {
        float* bin  = bufs[l & 1];
        float* bout = bufs[(l + 1) & 1];
        size_t woff = L1WOFF + (size_t)l * 2 * NCHL * BBLK;
        conv_a<<<convA_blocks_l, 256>>>(bin, HID, NCHL, 1);
        gemm_pack<<<gemm_grid, 256, SMEM_GEMM>>>(NCHL, woff, bb + l * HID,
                                                 yrel, bout);
        gather_add<<<gat_blocks, 256>>>(yrel, bout);
    }
    // Final conv output (pre-relu) is in buf0.

    pool_kernel<<<NGRAPHS, 128>>>(buf0, batch, pool);
    mlp_kernel<<<NGRAPHS, 128>>>(pool, lw1, lb1, m1, HID, HID, 1);
    mlp_kernel<<<NGRAPHS, 128>>>(m1,   lw2, lb2, m2, HID, HID, 1);
    mlp_kernel<<<NGRAPHS, 128>>>(m2,   lw3, lb3, out, HID, NOUT, 0);
}

// round 7
// speedup vs baseline: 2.8054x; 2.1668x over previous
#include <cuda_runtime.h>
#include <cuda_bf16.h>
#include <cstdint>

// Problem constants (fixed-shape problem)
#define NNODES 50000
#define NEDGES 800000
#define NGRAPHS 256
#define HID 100
#define K1 336
#define NOUT 29

#define NBLK 391            // ceil(50000/128)
#define NCH1 21             // layer-1 K chunks of 16 (336/16)
#define NCHL 7              // layer-2..5 K chunks (112/16, zero-padded)
#define CBLK 2048           // uint32 per 128x16 chunk block (hi 1024 + lo 1024)
#define L1WOFF (2 * NCH1 * CBLK)

// Scratch (device globals — allocation-free rule)
__device__ float g_yrel[NNODES * HID];
__device__ float g_buf0[NNODES * HID];
__device__ float g_buf1[NNODES * HID];
__device__ float g_pool[NGRAPHS * HID];
__device__ float g_m1[NGRAPHS * HID];
__device__ float g_m2[NGRAPHS * HID];

// Packed bf16 hi/lo operands (fragment-ordered)
__device__ unsigned g_apack[(size_t)NBLK * NCH1 * CBLK];          // 67 MB
__device__ unsigned g_wpack[L1WOFF + 4 * 2 * NCHL * CBLK];        // 0.8 MB

// CSR scratch
__device__ int g_cnt[NNODES];
__device__ int g_cur[NNODES];
__device__ int g_offs[NNODES + 1];
__device__ int g_csr_src[NEDGES];
#define SCAN_B 512
#define NSCAN ((NNODES + SCAN_B - 1) / SCAN_B)   // 98
__device__ int g_bsum[NSCAN];

// ---------------------------------------------------------------------------
// bf16 helpers
// ---------------------------------------------------------------------------
__device__ __forceinline__ uint32_t packbf(float e0, float e1) {
    __nv_bfloat162 h = __floats2bfloat162_rn(e0, e1);   // .x = e0 (low)
    return *reinterpret_cast<uint32_t*>(&h);
}
__device__ __forceinline__ float bfres(float a) {
    return a - __bfloat162float(__float2bfloat16_rn(a));
}

__device__ __forceinline__ void mma_bf16(float* d, const uint32_t* a,
                                         const uint32_t* b) {
    asm volatile(
        "mma.sync.aligned.m16n8k16.row.col.f32.bf16.bf16.f32 "
        "{%0,%1,%2,%3}, {%4,%5,%6,%7}, {%8,%9}, {%0,%1,%2,%3};"
        : "+f"(d[0]), "+f"(d[1]), "+f"(d[2]), "+f"(d[3])
        : "r"(a[0]), "r"(a[1]), "r"(a[2]), "r"(a[3]),
          "r"(b[0]), "r"(b[1]));
}

__device__ __forceinline__ uint32_t smem_u32(const void* p) {
    uint32_t a;
    asm("{ .reg .u64 t; cvta.to.shared.u64 t, %1; cvt.u32.u64 %0, t; }"
        : "=r"(a) : "l"(p));
    return a;
}

#define CP_ASYNC16(dst_u32, src_ptr) \
    asm volatile("cp.async.cg.shared.global [%0], [%1], 16;" \
                 :: "r"(dst_u32), "l"(src_ptr))
#define CP_COMMIT() asm volatile("cp.async.commit_group;")
#define CP_WAIT1()  asm volatile("cp.async.wait_group 1;")
#define CP_WAIT0()  asm volatile("cp.async.wait_group 0;")

// ---------------------------------------------------------------------------
// conv_a: activations -> bf16 hi/lo A-pack, m16n8k16 fragment order.
// One block per (128-row block b, chunk ch); thread = (mtile t, lane).
// Lane owns rows {r0, r0+8}, k pairs {k0,k0+1} and {k0+8,k0+9}:
//   hi regs: {(r0,k0),(r1,k0),(r0,k0+8),(r1,k0+8)} -> one uint4; lo at +1024.
// ---------------------------------------------------------------------------
__global__ __launch_bounds__(256) void conv_a(
    const float* __restrict__ src, int K, int nch, int doRelu)
{
    const int lane = threadIdx.x & 31;
    const int t = threadIdx.x >> 5;
    const int ch = blockIdx.x % nch;
    const int b = blockIdx.x / nch;

    const int r0 = b * 128 + t * 16 + (lane >> 2);
    const int r1 = r0 + 8;
    const int k0 = ch * 16 + (lane & 3) * 2;

    float v[2][4];   // [row][elem: k0,k0+1,k0+8,k0+9]
#pragma unroll
    for (int i = 0; i < 2; i++) {
        const int r = i ? r1 : r0;
        const float* Ar = src + (size_t)r * K;
#pragma unroll
        for (int j = 0; j < 4; j++) {
            const int kk = k0 + (j >> 1) * 8 + (j & 1);
            float x = (r < NNODES && kk < K) ? Ar[kk] : 0.f;
            if (doRelu) x = fmaxf(x, 0.f);
            v[i][j] = x;
        }
    }

    unsigned* base = g_apack + (size_t)blockIdx.x * CBLK + (t * 32 + lane) * 4;
    uint4 hi, lo;
    hi.x = packbf(v[0][0], v[0][1]);
    hi.y = packbf(v[1][0], v[1][1]);
    hi.z = packbf(v[0][2], v[0][3]);
    hi.w = packbf(v[1][2], v[1][3]);
    lo.x = packbf(bfres(v[0][0]), bfres(v[0][1]));
    lo.y = packbf(bfres(v[1][0]), bfres(v[1][1]));
    lo.z = packbf(bfres(v[0][2]), bfres(v[0][3]));
    lo.w = packbf(bfres(v[1][2]), bfres(v[1][3]));
    *(uint4*)base = hi;
    *(uint4*)(base + 1024) = lo;
}

// ---------------------------------------------------------------------------
// pack_weights: all 5 layers' W -> bf16 hi/lo B-pack, fragment order.
// B frag (16k x 8n tile): lane owns col n = u*8 + lane>>2,
//   reg0 = (k0,k0+1), reg1 = (k0+8,k0+9); lo at +1024.
// ---------------------------------------------------------------------------
__global__ __launch_bounds__(256) void pack_weights(
    const float* __restrict__ w1_rel, const float* __restrict__ w1_root,
    const float* __restrict__ w_rel, const float* __restrict__ w_root)
{
    const int layer = blockIdx.y;
    const int K = layer ? HID : K1;
    const int nch = layer ? NCHL : NCH1;
    const int idx = blockIdx.x * 256 + threadIdx.x;
    if (idx >= 2 * 16 * 32 * nch) return;
    const int ch = idx % nch;
    int rest = idx / nch;
    const int lane = rest & 31; rest >>= 5;
    const int u = rest & 15;
    const int y = rest >> 4;

    const float* W;
    if (layer == 0) W = y ? w1_root : w1_rel;
    else W = (y ? w_root : w_rel) + (size_t)(layer - 1) * HID * HID;

    const int n = u * 8 + (lane >> 2);
    const int k0 = ch * 16 + (lane & 3) * 2;
    float v[4];
#pragma unroll
    for (int j = 0; j < 4; j++) {
        const int kk = k0 + (j >> 1) * 8 + (j & 1);
        v[j] = (n < HID && kk < K) ? W[(size_t)n * K + kk] : 0.f;
    }

    const size_t loff = layer ? (L1WOFF + (size_t)(layer - 1) * 2 * NCHL * CBLK) : 0;
    unsigned* base = g_wpack + loff + (size_t)(y * nch + ch) * CBLK
                     + (u * 32 + lane) * 2;
    uint2 hi, lo;
    hi.x = packbf(v[0], v[1]);
    hi.y = packbf(v[2], v[3]);
    lo.x = packbf(bfres(v[0]), bfres(v[1]));
    lo.y = packbf(bfres(v[2]), bfres(v[3]));
    *(uint2*)base = hi;
    *(uint2*)(base + 1024) = lo;
}

// ---------------------------------------------------------------------------
// gemm_bf16: 128x128 tile from packed operands, 2-split bf16 (3 MMA passes).
// grid (NBLK, 2): y==0 -> Yrel, y==1 -> Agg (+bias). Double-buffered cp.async.
// Dyn smem (u32): sA[2][2048] | sB[2][2048] | bias f32[128]  (33280 B)
// ---------------------------------------------------------------------------
__global__ __launch_bounds__(256, 2) void gemm_bf16(
    int nch, size_t woff, const float* __restrict__ bias,
    float* __restrict__ Yrel, float* __restrict__ Agg)
{
    extern __shared__ unsigned smem_u[];
    float* sbias = (float*)(smem_u + 8192);

    const int tid = threadIdx.x;
    const int lane = tid & 31;
    const int warp = tid >> 5;
    const int wm = warp & 1;
    const int wn = warp >> 1;
    const int b = blockIdx.x;
    const int y = blockIdx.y;
    const int row0 = b * 128;

    if (tid < HID) sbias[tid] = y ? bias[tid] : 0.f;
    else if (tid < 128) sbias[tid] = 0.f;

    const unsigned* ab = g_apack + (size_t)b * nch * CBLK;
    const unsigned* wb = g_wpack + woff + (size_t)y * nch * CBLK;
    const uint32_t smb = smem_u32(smem_u);
    const int off = tid * 8;

    // prefetch chunk 0 into buffer 0
    {
        const unsigned* sa = ab + off;
        const unsigned* sw = wb + off;
        uint32_t da = smb + (uint32_t)off * 4;
        uint32_t db = smb + (uint32_t)(4096 + off) * 4;
        CP_ASYNC16(da, sa); CP_ASYNC16(da + 16, sa + 4);
        CP_ASYNC16(db, sw); CP_ASYNC16(db + 16, sw + 4);
        CP_COMMIT();
    }

    float acc[4][4][4];
#pragma unroll
    for (int mt = 0; mt < 4; mt++)
#pragma unroll
        for (int nt = 0; nt < 4; nt++)
#pragma unroll
            for (int e = 0; e < 4; e++) acc[mt][nt][e] = 0.f;

    for (int ch = 0; ch < nch; ch++) {
        if (ch + 1 < nch) {
            const int nb = (ch + 1) & 1;
            const unsigned* sa = ab + (size_t)(ch + 1) * CBLK + off;
            const unsigned* sw = wb + (size_t)(ch + 1) * CBLK + off;
            uint32_t da = smb + (uint32_t)(nb * 2048 + off) * 4;
            uint32_t db = smb + (uint32_t)(4096 + nb * 2048 + off) * 4;
            CP_ASYNC16(da, sa); CP_ASYNC16(da + 16, sa + 4);
            CP_ASYNC16(db, sw); CP_ASYNC16(db + 16, sw + 4);
            CP_COMMIT();
            CP_WAIT1();
        } else {
            CP_WAIT0();
        }
        __syncthreads();

        const int buf = ch & 1;
        const unsigned* Ah = smem_u + buf * 2048;
        const unsigned* Al = Ah + 1024;
        const unsigned* Bh = smem_u + 4096 + buf * 2048;
        const unsigned* Bl = Bh + 1024;

        uint32_t af[4][4], bh[4][2], bl[4][2];
#pragma unroll
        for (int mt = 0; mt < 4; mt++) {
            uint4 q = *(const uint4*)&Ah[((wm * 4 + mt) * 32 + lane) * 4];
            af[mt][0] = q.x; af[mt][1] = q.y; af[mt][2] = q.z; af[mt][3] = q.w;
        }
#pragma unroll
        for (int nt = 0; nt < 4; nt++) {
            uint2 qh = *(const uint2*)&Bh[((wn * 4 + nt) * 32 + lane) * 2];
            bh[nt][0] = qh.x; bh[nt][1] = qh.y;
            uint2 ql = *(const uint2*)&Bl[((wn * 4 + nt) * 32 + lane) * 2];
            bl[nt][0] = ql.x; bl[nt][1] = ql.y;
        }
        // pass0: Ahi*Bhi, pass1: Ahi*Blo
#pragma unroll
        for (int mt = 0; mt < 4; mt++)
#pragma unroll
            for (int nt = 0; nt < 4; nt++) {
                mma_bf16(acc[mt][nt], af[mt], bh[nt]);
                mma_bf16(acc[mt][nt], af[mt], bl[nt]);
            }
        // reload af <- Alo; pass2: Alo*Bhi
#pragma unroll
        for (int mt = 0; mt < 4; mt++) {
            uint4 q = *(const uint4*)&Al[((wm * 4 + mt) * 32 + lane) * 4];
            af[mt][0] = q.x; af[mt][1] = q.y; af[mt][2] = q.z; af[mt][3] = q.w;
        }
#pragma unroll
        for (int mt = 0; mt < 4; mt++)
#pragma unroll
            for (int nt = 0; nt < 4; nt++)
                mma_bf16(acc[mt][nt], af[mt], bh[nt]);
        __syncthreads();
    }

    // epilogue: c-fragment scatter (layout identical to R5/R6, validated)
    float* O = y ? Agg : Yrel;
    const int rbase = row0 + wm * 64 + (lane >> 2);
    const int cbase = wn * 32 + (lane & 3) * 2;
#pragma unroll
    for (int mt = 0; mt < 4; mt++) {
#pragma unroll
        for (int nt = 0; nt < 4; nt++) {
            int col = cbase + nt * 8;
            if (col >= HID) continue;
            float bx = sbias[col], by = sbias[col + 1];
            int r0 = rbase + mt * 16;
            if (r0 < NNODES) {
                float2 v = make_float2(acc[mt][nt][0] + bx, acc[mt][nt][1] + by);
                *(float2*)(O + (size_t)r0 * HID + col) = v;
            }
            int r1 = r0 + 8;
            if (r1 < NNODES) {
                float2 v = make_float2(acc[mt][nt][2] + bx, acc[mt][nt][3] + by);
                *(float2*)(O + (size_t)r1 * HID + col) = v;
            }
        }
    }
}

// ---------------------------------------------------------------------------
// CSR build: count -> scan (two-level) -> fill
// ---------------------------------------------------------------------------
__global__ __launch_bounds__(256) void csr_zero() {
    int i = blockIdx.x * blockDim.x + threadIdx.x;
    if (i < NNODES) { g_cnt[i] = 0; g_cur[i] = 0; }
    if (i == 0) g_offs[0] = 0;
}

__global__ __launch_bounds__(256) void csr_count(const int* __restrict__ dst) {
    int e = blockIdx.x * blockDim.x + threadIdx.x;
    if (e < NEDGES) atomicAdd(&g_cnt[dst[e]], 1);
}

__global__ __launch_bounds__(SCAN_B) void csr_scan_local() {
    __shared__ int sh[SCAN_B];
    int tid = threadIdx.x;
    int idx = blockIdx.x * SCAN_B + tid;
    int v = (idx < NNODES) ? g_cnt[idx] : 0;
    sh[tid] = v;
    __syncthreads();
#pragma unroll
    for (int d = 1; d < SCAN_B; d <<= 1) {
        int t = (tid >= d) ? sh[tid - d] : 0;
        __syncthreads();
        sh[tid] += t;
        __syncthreads();
    }
    if (idx < NNODES) g_offs[idx + 1] = sh[tid];
    if (tid == SCAN_B - 1) g_bsum[blockIdx.x] = sh[tid];
}

__global__ __launch_bounds__(128) void csr_scan_bsums() {
    __shared__ int sh[128];
    int tid = threadIdx.x;
    sh[tid] = (tid < NSCAN) ? g_bsum[tid] : 0;
    __syncthreads();
#pragma unroll
    for (int d = 1; d < 128; d <<= 1) {
        int t = (tid >= d) ? sh[tid - d] : 0;
        __syncthreads();
        sh[tid] += t;
        __syncthreads();
    }
    if (tid < NSCAN) g_bsum[tid] = (tid == 0) ? 0 : sh[tid - 1];
}

__global__ __launch_bounds__(256) void csr_scan_add() {
    int idx = blockIdx.x * blockDim.x + threadIdx.x;
    if (idx < NNODES) g_offs[idx + 1] += g_bsum[idx / SCAN_B];
}

__global__ __launch_bounds__(256) void csr_fill(const int* __restrict__ src,
                                                const int* __restrict__ dst) {
    int e = blockIdx.x * blockDim.x + threadIdx.x;
    if (e < NEDGES) {
        int d = dst[e];
        int pos = g_offs[d] + atomicAdd(&g_cur[d], 1);
        g_csr_src[pos] = src[e];
    }
}

// ---------------------------------------------------------------------------
// Gather aggregate: out[node,:] += sum_{e in csr[node]} yrel[src_e,:]
// ---------------------------------------------------------------------------
__global__ __launch_bounds__(256) void gather_add(
    const float* __restrict__ yrel, float* __restrict__ out)
{
    int node = blockIdx.x * 8 + (threadIdx.x >> 5);
    int lane = threadIdx.x & 31;
    if (node >= NNODES || lane >= HID / 4) return;
    int beg = g_offs[node];
    int end = g_offs[node + 1];
    const float4* base = (const float4*)yrel;
    float4* op = (float4*)(out + (size_t)node * HID);
    float4 acc = op[lane];  // root + bias already there
    int e = beg;
    for (; e + 1 < end; e += 2) {
        int s0 = g_csr_src[e];
        int s1 = g_csr_src[e + 1];
        float4 v0 = base[(size_t)s0 * (HID / 4) + lane];
        float4 v1 = base[(size_t)s1 * (HID / 4) + lane];
        acc.x += v0.x + v1.x;
        acc.y += v0.y + v1.y;
        acc.z += v0.z + v1.z;
        acc.w += v0.w + v1.w;
    }
    if (e < end) {
        int s0 = g_csr_src[e];
        float4 v0 = base[(size_t)s0 * (HID / 4) + lane];
        acc.x += v0.x; acc.y += v0.y; acc.z += v0.z; acc.w += v0.w;
    }
    op[lane] = acc;
}

// ---------------------------------------------------------------------------
// Mean pool over sorted batch (relu folded in)
// ---------------------------------------------------------------------------
__device__ __forceinline__ int lower_bound_i(const int* a, int n, int key) {
    int lo = 0, hi = n;
    while (lo < hi) {
        int mid = (lo + hi) >> 1;
        if (a[mid] < key) lo = mid + 1; else hi = mid;
    }
    return lo;
}

__global__ __launch_bounds__(128) void pool_kernel(
    const float* __restrict__ h, const int* __restrict__ batch,
    float* __restrict__ pooled)
{
    int g = blockIdx.x;
    __shared__ int s_se[2];
    if (threadIdx.x == 0) {
        s_se[0] = lower_bound_i(batch, NNODES, g);
        s_se[1] = lower_bound_i(batch, NNODES, g + 1);
    }
    __syncthreads();
    int start = s_se[0], end = s_se[1];
    int c = threadIdx.x;
    if (c < HID) {
        float s = 0.f;
        for (int i = start; i < end; i++)
            s += fmaxf(h[(size_t)i * HID + c], 0.f);
        float cnt = (float)((end - start) > 0 ? (end - start) : 1);
        pooled[g * HID + c] = s / cnt;
    }
}

// ---------------------------------------------------------------------------
// Small MLP layer
// ---------------------------------------------------------------------------
__global__ __launch_bounds__(128) void mlp_kernel(
    const float* __restrict__ in, const float* __restrict__ W,
    const float* __restrict__ bv, float* __restrict__ out,
    int Kin, int Nout, int doRelu)
{
    int g = blockIdx.x;
    __shared__ float sin_[128];
    if (threadIdx.x < Kin) sin_[threadIdx.x] = in[g * Kin + threadIdx.x];
    __syncthreads();
    int c = threadIdx.x;
    if (c < Nout) {
        float s = bv[c];
        const float* wr = W + (size_t)c * Kin;
        for (int k = 0; k < Kin; k++) s = fmaf(sin_[k], wr[k], s);
        if (doRelu) s = fmaxf(s, 0.f);
        out[g * Nout + c] = s;
    }
}

// ---------------------------------------------------------------------------
extern "C" void kernel_launch(void* const* d_in, const int* in_sizes, int n_in,
                              void* d_out, int out_size)
{
    const float* x       = (const float*)d_in[0];
    const int*   ei      = (const int*)  d_in[1];
    const int*   batch   = (const int*)  d_in[2];
    const float* w1_rel  = (const float*)d_in[3];
    const float* w1_root = (const float*)d_in[4];
    const float* b1      = (const float*)d_in[5];
    const float* w_rel   = (const float*)d_in[6];   // [4,100,100]
    const float* w_root  = (const float*)d_in[7];   // [4,100,100]
    const float* bb      = (const float*)d_in[8];   // [4,100]
    const float* lw1     = (const float*)d_in[9];
    const float* lb1     = (const float*)d_in[10];
    const float* lw2     = (const float*)d_in[11];
    const float* lb2     = (const float*)d_in[12];
    const float* lw3     = (const float*)d_in[13];
    const float* lb3     = (const float*)d_in[14];
    float* out = (float*)d_out;

    const int* src = ei;
    const int* dst = ei + NEDGES;

    float *yrel, *buf0, *buf1, *pool, *m1, *m2;
    cudaGetSymbolAddress((void**)&yrel, g_yrel);
    cudaGetSymbolAddress((void**)&buf0, g_buf0);
    cudaGetSymbolAddress((void**)&buf1, g_buf1);
    cudaGetSymbolAddress((void**)&pool, g_pool);
    cudaGetSymbolAddress((void**)&m1,   g_m1);
    cudaGetSymbolAddress((void**)&m2,   g_m2);

    const int SMEM_GEMM = (8192 + 128) * 4;   // 33280 B
    cudaFuncSetAttribute(gemm_bf16,
                         cudaFuncAttributeMaxDynamicSharedMemorySize, SMEM_GEMM);

    dim3 gemm_grid(NBLK, 2);
    const int gat_blocks = (NNODES + 7) / 8;
    const dim3 packw_grid((2 * 16 * 32 * NCH1 + 255) / 256, 5);

    // Launch order puts the layer-1 GEMM at index 3 (the profiled slot).
    csr_zero<<<(NNODES + 255) / 256, 256>>>();                          // 0
    conv_a<<<NBLK * NCH1, 256>>>(x, K1, NCH1, 0);                       // 1
    pack_weights<<<packw_grid, 256>>>(w1_rel, w1_root, w_rel, w_root);  // 2
    gemm_bf16<<<gemm_grid, 256, SMEM_GEMM>>>(NCH1, 0, b1, yrel, buf0);  // 3
    csr_count<<<(NEDGES + 255) / 256, 256>>>(dst);                      // 4
    csr_scan_local<<<NSCAN, SCAN_B>>>();
    csr_scan_bsums<<<1, 128>>>();
    csr_scan_add<<<(NNODES + 255) / 256, 256>>>();
    csr_fill<<<(NEDGES + 255) / 256, 256>>>(src, dst);
    gather_add<<<gat_blocks, 256>>>(yrel, buf0);

    // Layers 2..5 (relu folded into conv_a)
    float* bufs[2] = { buf0, buf1 };
    for (int l = 0; l < 4; l++) {
        float* bin  = bufs[l & 1];
        float* bout = bufs[(l + 1) & 1];
        size_t woff = L1WOFF + (size_t)l * 2 * NCHL * CBLK;
        conv_a<<<NBLK * NCHL, 256>>>(bin, HID, NCHL, 1);
        gemm_bf16<<<gemm_grid, 256, SMEM_GEMM>>>(NCHL, woff, bb + l * HID,
                                                 yrel, bout);
        gather_add<<<gat_blocks, 256>>>(yrel, bout);
    }
    // Final conv output (pre-relu) is in buf0.

    pool_kernel<<<NGRAPHS, 128>>>(buf0, batch, pool);
    mlp_kernel<<<NGRAPHS, 128>>>(pool, lw1, lb1, m1, HID, HID, 1);
    mlp_kernel<<<NGRAPHS, 128>>>(m1,   lw2, lb2, m2, HID, HID, 1);
    mlp_kernel<<<NGRAPHS, 128>>>(m2,   lw3, lb3, out, HID, NOUT, 0);
}

// round 8
// speedup vs baseline: 3.0494x; 1.0870x over previous
#include <cuda_runtime.h>
#include <cuda_bf16.h>
#include <cuda_fp16.h>
#include <cstdint>

// Problem constants (fixed-shape problem)
#define NNODES 50000
#define NEDGES 800000
#define NGRAPHS 256
#define HID 100
#define K1 336
#define NOUT 29

#define NBLK 391            // ceil(50000/128)
#define NCH1 21             // layer-1 K chunks of 16 (336/16)
#define NCHL 7              // layer-2..5 K chunks (112/16, zero-padded)
#define CBLK 2048           // uint32 per 128x16 chunk block (hi 1024 + lo 1024)
#define L1WOFF (2 * NCH1 * CBLK)

// Scratch (device globals — allocation-free rule)
__device__ __half g_yrelh[NNODES * HID];    // fp16 yrel (gather operand)
__device__ float g_buf0[NNODES * HID];
__device__ float g_buf1[NNODES * HID];
__device__ float g_pool[NGRAPHS * HID];
__device__ float g_m1[NGRAPHS * HID];
__device__ float g_m2[NGRAPHS * HID];

// Packed bf16 hi/lo operands (fragment-ordered)
__device__ unsigned g_apack[(size_t)NBLK * NCH1 * CBLK];          // 67 MB
__device__ unsigned g_wpack[L1WOFF + 4 * 2 * NCHL * CBLK];        // 0.8 MB

// CSR scratch
__device__ int g_cnt[NNODES];
__device__ int g_cur[NNODES];
__device__ int g_offs[NNODES + 1];
__device__ int g_csr_src[NEDGES];
#define SCAN_B 512
#define NSCAN ((NNODES + SCAN_B - 1) / SCAN_B)   // 98
__device__ int g_bsum[NSCAN];

// ---------------------------------------------------------------------------
// bf16 helpers
// ---------------------------------------------------------------------------
__device__ __forceinline__ uint32_t packbf(float e0, float e1) {
    __nv_bfloat162 h = __floats2bfloat162_rn(e0, e1);   // .x = e0 (low)
    return *reinterpret_cast<uint32_t*>(&h);
}
__device__ __forceinline__ float bfres(float a) {
    return a - __bfloat162float(__float2bfloat16_rn(a));
}

__device__ __forceinline__ void mma_bf16(float* d, const uint32_t* a,
                                         const uint32_t* b) {
    asm volatile(
        "mma.sync.aligned.m16n8k16.row.col.f32.bf16.bf16.f32 "
        "{%0,%1,%2,%3}, {%4,%5,%6,%7}, {%8,%9}, {%0,%1,%2,%3};"
        : "+f"(d[0]), "+f"(d[1]), "+f"(d[2]), "+f"(d[3])
        : "r"(a[0]), "r"(a[1]), "r"(a[2]), "r"(a[3]),
          "r"(b[0]), "r"(b[1]));
}

__device__ __forceinline__ uint32_t smem_u32(const void* p) {
    uint32_t a;
    asm("{ .reg .u64 t; cvta.to.shared.u64 t, %1; cvt.u32.u64 %0, t; }"
        : "=r"(a) : "l"(p));
    return a;
}

#define CP_ASYNC16(dst_u32, src_ptr) \
    asm volatile("cp.async.cg.shared.global [%0], [%1], 16;" \
                 :: "r"(dst_u32), "l"(src_ptr))
#define CP_COMMIT() asm volatile("cp.async.commit_group;")
#define CP_WAIT1()  asm volatile("cp.async.wait_group 1;")
#define CP_WAIT0()  asm volatile("cp.async.wait_group 0;")

// ---------------------------------------------------------------------------
// conv_a: activations -> bf16 hi/lo A-pack, m16n8k16 fragment order.
// (unchanged from R7 — validated)
// ---------------------------------------------------------------------------
__global__ __launch_bounds__(256) void conv_a(
    const float* __restrict__ src, int K, int nch, int doRelu)
{
    const int lane = threadIdx.x & 31;
    const int t = threadIdx.x >> 5;
    const int ch = blockIdx.x % nch;
    const int b = blockIdx.x / nch;

    const int r0 = b * 128 + t * 16 + (lane >> 2);
    const int r1 = r0 + 8;
    const int k0 = ch * 16 + (lane & 3) * 2;

    float v[2][4];
#pragma unroll
    for (int i = 0; i < 2; i++) {
        const int r = i ? r1 : r0;
        const float* Ar = src + (size_t)r * K;
#pragma unroll
        for (int j = 0; j < 4; j++) {
            const int kk = k0 + (j >> 1) * 8 + (j & 1);
            float x = (r < NNODES && kk < K) ? Ar[kk] : 0.f;
            if (doRelu) x = fmaxf(x, 0.f);
            v[i][j] = x;
        }
    }

    unsigned* base = g_apack + (size_t)blockIdx.x * CBLK + (t * 32 + lane) * 4;
    uint4 hi, lo;
    hi.x = packbf(v[0][0], v[0][1]);
    hi.y = packbf(v[1][0], v[1][1]);
    hi.z = packbf(v[0][2], v[0][3]);
    hi.w = packbf(v[1][2], v[1][3]);
    lo.x = packbf(bfres(v[0][0]), bfres(v[0][1]));
    lo.y = packbf(bfres(v[1][0]), bfres(v[1][1]));
    lo.z = packbf(bfres(v[0][2]), bfres(v[0][3]));
    lo.w = packbf(bfres(v[1][2]), bfres(v[1][3]));
    *(uint4*)base = hi;
    *(uint4*)(base + 1024) = lo;
}

// ---------------------------------------------------------------------------
// pack_weights: all 5 layers' W -> bf16 hi/lo B-pack (unchanged from R7)
// ---------------------------------------------------------------------------
__global__ __launch_bounds__(256) void pack_weights(
    const float* __restrict__ w1_rel, const float* __restrict__ w1_root,
    const float* __restrict__ w_rel, const float* __restrict__ w_root)
{
    const int layer = blockIdx.y;
    const int K = layer ? HID : K1;
    const int nch = layer ? NCHL : NCH1;
    const int idx = blockIdx.x * 256 + threadIdx.x;
    if (idx >= 2 * 16 * 32 * nch) return;
    const int ch = idx % nch;
    int rest = idx / nch;
    const int lane = rest & 31; rest >>= 5;
    const int u = rest & 15;
    const int y = rest >> 4;

    const float* W;
    if (layer == 0) W = y ? w1_root : w1_rel;
    else W = (y ? w_root : w_rel) + (size_t)(layer - 1) * HID * HID;

    const int n = u * 8 + (lane >> 2);
    const int k0 = ch * 16 + (lane & 3) * 2;
    float v[4];
#pragma unroll
    for (int j = 0; j < 4; j++) {
        const int kk = k0 + (j >> 1) * 8 + (j & 1);
        v[j] = (n < HID && kk < K) ? W[(size_t)n * K + kk] : 0.f;
    }

    const size_t loff = layer ? (L1WOFF + (size_t)(layer - 1) * 2 * NCHL * CBLK) : 0;
    unsigned* base = g_wpack + loff + (size_t)(y * nch + ch) * CBLK
                     + (u * 32 + lane) * 2;
    uint2 hi, lo;
    hi.x = packbf(v[0], v[1]);
    hi.y = packbf(v[2], v[3]);
    lo.x = packbf(bfres(v[0]), bfres(v[1]));
    lo.y = packbf(bfres(v[2]), bfres(v[3]));
    *(uint2*)base = hi;
    *(uint2*)(base + 1024) = lo;
}

// ---------------------------------------------------------------------------
// gemm_bf16: 128x128 tile, 2-split bf16 (3 MMA passes). grid (NBLK, 2).
// y==0 -> yrel as FP16 (half2 stores), y==1 -> Agg fp32 (+bias).
// ---------------------------------------------------------------------------
__global__ __launch_bounds__(256, 2) void gemm_bf16(
    int nch, size_t woff, const float* __restrict__ bias,
    float* __restrict__ Agg)
{
    extern __shared__ unsigned smem_u[];
    float* sbias = (float*)(smem_u + 8192);

    const int tid = threadIdx.x;
    const int lane = tid & 31;
    const int warp = tid >> 5;
    const int wm = warp & 1;
    const int wn = warp >> 1;
    const int b = blockIdx.x;
    const int y = blockIdx.y;
    const int row0 = b * 128;

    if (tid < HID) sbias[tid] = y ? bias[tid] : 0.f;
    else if (tid < 128) sbias[tid] = 0.f;

    const unsigned* ab = g_apack + (size_t)b * nch * CBLK;
    const unsigned* wb = g_wpack + woff + (size_t)y * nch * CBLK;
    const uint32_t smb = smem_u32(smem_u);
    const int off = tid * 8;

    // prefetch chunk 0 into buffer 0
    {
        const unsigned* sa = ab + off;
        const unsigned* sw = wb + off;
        uint32_t da = smb + (uint32_t)off * 4;
        uint32_t db = smb + (uint32_t)(4096 + off) * 4;
        CP_ASYNC16(da, sa); CP_ASYNC16(da + 16, sa + 4);
        CP_ASYNC16(db, sw); CP_ASYNC16(db + 16, sw + 4);
        CP_COMMIT();
    }

    float acc[4][4][4];
#pragma unroll
    for (int mt = 0; mt < 4; mt++)
#pragma unroll
        for (int nt = 0; nt < 4; nt++)
#pragma unroll
            for (int e = 0; e < 4; e++) acc[mt][nt][e] = 0.f;

    for (int ch = 0; ch < nch; ch++) {
        if (ch + 1 < nch) {
            const int nb = (ch + 1) & 1;
            const unsigned* sa = ab + (size_t)(ch + 1) * CBLK + off;
            const unsigned* sw = wb + (size_t)(ch + 1) * CBLK + off;
            uint32_t da = smb + (uint32_t)(nb * 2048 + off) * 4;
            uint32_t db = smb + (uint32_t)(4096 + nb * 2048 + off) * 4;
            CP_ASYNC16(da, sa); CP_ASYNC16(da + 16, sa + 4);
            CP_ASYNC16(db, sw); CP_ASYNC16(db + 16, sw + 4);
            CP_COMMIT();
            CP_WAIT1();
        } else {
            CP_WAIT0();
        }
        __syncthreads();

        const int buf = ch & 1;
        const unsigned* Ah = smem_u + buf * 2048;
        const unsigned* Al = Ah + 1024;
        const unsigned* Bh = smem_u + 4096 + buf * 2048;
        const unsigned* Bl = Bh + 1024;

        uint32_t af[4][4], bh[4][2], bl[4][2];
#pragma unroll
        for (int mt = 0; mt < 4; mt++) {
            uint4 q = *(const uint4*)&Ah[((wm * 4 + mt) * 32 + lane) * 4];
            af[mt][0] = q.x; af[mt][1] = q.y; af[mt][2] = q.z; af[mt][3] = q.w;
        }
#pragma unroll
        for (int nt = 0; nt < 4; nt++) {
            uint2 qh = *(const uint2*)&Bh[((wn * 4 + nt) * 32 + lane) * 2];
            bh[nt][0] = qh.x; bh[nt][1] = qh.y;
            uint2 ql = *(const uint2*)&Bl[((wn * 4 + nt) * 32 + lane) * 2];
            bl[nt][0] = ql.x; bl[nt][1] = ql.y;
        }
#pragma unroll
        for (int mt = 0; mt < 4; mt++)
#pragma unroll
            for (int nt = 0; nt < 4; nt++) {
                mma_bf16(acc[mt][nt], af[mt], bh[nt]);
                mma_bf16(acc[mt][nt], af[mt], bl[nt]);
            }
#pragma unroll
        for (int mt = 0; mt < 4; mt++) {
            uint4 q = *(const uint4*)&Al[((wm * 4 + mt) * 32 + lane) * 4];
            af[mt][0] = q.x; af[mt][1] = q.y; af[mt][2] = q.z; af[mt][3] = q.w;
        }
#pragma unroll
        for (int mt = 0; mt < 4; mt++)
#pragma unroll
            for (int nt = 0; nt < 4; nt++)
                mma_bf16(acc[mt][nt], af[mt], bh[nt]);
        __syncthreads();
    }

    // epilogue: c-fragment scatter (layout validated R5-R7)
    const int rbase = row0 + wm * 64 + (lane >> 2);
    const int cbase = wn * 32 + (lane & 3) * 2;
    if (y == 0) {
        // yrel -> fp16 (no bias)
#pragma unroll
        for (int mt = 0; mt < 4; mt++) {
#pragma unroll
            for (int nt = 0; nt < 4; nt++) {
                int col = cbase + nt * 8;
                if (col >= HID) continue;
                int r0 = rbase + mt * 16;
                if (r0 < NNODES)
                    *(__half2*)(g_yrelh + (size_t)r0 * HID + col) =
                        __floats2half2_rn(acc[mt][nt][0], acc[mt][nt][1]);
                int r1 = r0 + 8;
                if (r1 < NNODES)
                    *(__half2*)(g_yrelh + (size_t)r1 * HID + col) =
                        __floats2half2_rn(acc[mt][nt][2], acc[mt][nt][3]);
            }
        }
    } else {
#pragma unroll
        for (int mt = 0; mt < 4; mt++) {
#pragma unroll
            for (int nt = 0; nt < 4; nt++) {
                int col = cbase + nt * 8;
                if (col >= HID) continue;
                float bx = sbias[col], by = sbias[col + 1];
                int r0 = rbase + mt * 16;
                if (r0 < NNODES) {
                    float2 v = make_float2(acc[mt][nt][0] + bx, acc[mt][nt][1] + by);
                    *(float2*)(Agg + (size_t)r0 * HID + col) = v;
                }
                int r1 = r0 + 8;
                if (r1 < NNODES) {
                    float2 v = make_float2(acc[mt][nt][2] + bx, acc[mt][nt][3] + by);
                    *(float2*)(Agg + (size_t)r1 * HID + col) = v;
                }
            }
        }
    }
}

// ---------------------------------------------------------------------------
// CSR build: count -> scan (two-level) -> fill
// ---------------------------------------------------------------------------
__global__ __launch_bounds__(256) void csr_zero() {
    int i = blockIdx.x * blockDim.x + threadIdx.x;
    if (i < NNODES) { g_cnt[i] = 0; g_cur[i] = 0; }
    if (i == 0) g_offs[0] = 0;
}

__global__ __launch_bounds__(256) void csr_count(const int* __restrict__ dst) {
    int e = blockIdx.x * blockDim.x + threadIdx.x;
    if (e < NEDGES) atomicAdd(&g_cnt[dst[e]], 1);
}

__global__ __launch_bounds__(SCAN_B) void csr_scan_local() {
    __shared__ int sh[SCAN_B];
    int tid = threadIdx.x;
    int idx = blockIdx.x * SCAN_B + tid;
    int v = (idx < NNODES) ? g_cnt[idx] : 0;
    sh[tid] = v;
    __syncthreads();
#pragma unroll
    for (int d = 1; d < SCAN_B; d <<= 1) {
        int t = (tid >= d) ? sh[tid - d] : 0;
        __syncthreads();
        sh[tid] += t;
        __syncthreads();
    }
    if (idx < NNODES) g_offs[idx + 1] = sh[tid];
    if (tid == SCAN_B - 1) g_bsum[blockIdx.x] = sh[tid];
}

__global__ __launch_bounds__(128) void csr_scan_bsums() {
    __shared__ int sh[128];
    int tid = threadIdx.x;
    sh[tid] = (tid < NSCAN) ? g_bsum[tid] : 0;
    __syncthreads();
#pragma unroll
    for (int d = 1; d < 128; d <<= 1) {
        int t = (tid >= d) ? sh[tid - d] : 0;
        __syncthreads();
        sh[tid] += t;
        __syncthreads();
    }
    if (tid < NSCAN) g_bsum[tid] = (tid == 0) ? 0 : sh[tid - 1];
}

__global__ __launch_bounds__(256) void csr_scan_add() {
    int idx = blockIdx.x * blockDim.x + threadIdx.x;
    if (idx < NNODES) g_offs[idx + 1] += g_bsum[idx / SCAN_B];
}

__global__ __launch_bounds__(256) void csr_fill(const int* __restrict__ src,
                                                const int* __restrict__ dst) {
    int e = blockIdx.x * blockDim.x + threadIdx.x;
    if (e < NEDGES) {
        int d = dst[e];
        int pos = g_offs[d] + atomicAdd(&g_cur[d], 1);
        g_csr_src[pos] = src[e];
    }
}

// ---------------------------------------------------------------------------
// Gather aggregate (fp16 yrel): out[node,:] += sum yrelh[src_e,:]
// Warp per node; lane < 25 owns 4 features as one uint2 (2 x half2).
// ---------------------------------------------------------------------------
__global__ __launch_bounds__(256) void gather_add(float* __restrict__ out)
{
    int node = blockIdx.x * 8 + (threadIdx.x >> 5);
    int lane = threadIdx.x & 31;
    if (node >= NNODES || lane >= HID / 4) return;
    int beg = g_offs[node];
    int end = g_offs[node + 1];
    const uint2* base = (const uint2*)g_yrelh;   // 25 uint2 per row
    float4* op = (float4*)(out + (size_t)node * HID);
    float4 acc = op[lane];  // root + bias already there
    int e = beg;
    for (; e + 1 < end; e += 2) {
        int s0 = g_csr_src[e];
        int s1 = g_csr_src[e + 1];
        uint2 u0 = base[(size_t)s0 * 25 + lane];
        uint2 u1 = base[(size_t)s1 * 25 + lane];
        float2 a0 = __half22float2(*(__half2*)&u0.x);
        float2 a1 = __half22float2(*(__half2*)&u0.y);
        float2 b0 = __half22float2(*(__half2*)&u1.x);
        float2 b1 = __half22float2(*(__half2*)&u1.y);
        acc.x += a0.x + b0.x;
        acc.y += a0.y + b0.y;
        acc.z += a1.x + b1.x;
        acc.w += a1.y + b1.y;
    }
    if (e < end) {
        int s0 = g_csr_src[e];
        uint2 u0 = base[(size_t)s0 * 25 + lane];
        float2 a0 = __half22float2(*(__half2*)&u0.x);
        float2 a1 = __half22float2(*(__half2*)&u0.y);
        acc.x += a0.x; acc.y += a0.y; acc.z += a1.x; acc.w += a1.y;
    }
    op[lane] = acc;
}

// ---------------------------------------------------------------------------
// Mean pool over sorted batch (relu folded in)
// ---------------------------------------------------------------------------
__device__ __forceinline__ int lower_bound_i(const int* a, int n, int key) {
    int lo = 0, hi = n;
    while (lo < hi) {
        int mid = (lo + hi) >> 1;
        if (a[mid] < key) lo = mid + 1; else hi = mid;
    }
    return lo;
}

__global__ __launch_bounds__(128) void pool_kernel(
    const float* __restrict__ h, const int* __restrict__ batch,
    float* __restrict__ pooled)
{
    int g = blockIdx.x;
    __shared__ int s_se[2];
    if (threadIdx.x == 0) {
        s_se[0] = lower_bound_i(batch, NNODES, g);
        s_se[1] = lower_bound_i(batch, NNODES, g + 1);
    }
    __syncthreads();
    int start = s_se[0], end = s_se[1];
    int c = threadIdx.x;
    if (c < HID) {
        float s = 0.f;
        for (int i = start; i < end; i++)
            s += fmaxf(h[(size_t)i * HID + c], 0.f);
        float cnt = (float)((end - start) > 0 ? (end - start) : 1);
        pooled[g * HID + c] = s / cnt;
    }
}

// ---------------------------------------------------------------------------
// Small MLP layer
// ---------------------------------------------------------------------------
__global__ __launch_bounds__(128) void mlp_kernel(
    const float* __restrict__ in, const float* __restrict__ W,
    const float* __restrict__ bv, float* __restrict__ out,
    int Kin, int Nout, int doRelu)
{
    int g = blockIdx.x;
    __shared__ float sin_[128];
    if (threadIdx.x < Kin) sin_[threadIdx.x] = in[g * Kin + threadIdx.x];
    __syncthreads();
    int c = threadIdx.x;
    if (c < Nout) {
        float s = bv[c];
        const float* wr = W + (size_t)c * Kin;
        for (int k = 0; k < Kin; k++) s = fmaf(sin_[k], wr[k], s);
        if (doRelu) s = fmaxf(s, 0.f);
        out[g * Nout + c] = s;
    }
}

// ---------------------------------------------------------------------------
extern "C" void kernel_launch(void* const* d_in, const int* in_sizes, int n_in,
                              void* d_out, int out_size)
{
    const float* x       = (const float*)d_in[0];
    const int*   ei      = (const int*)  d_in[1];
    const int*   batch   = (const int*)  d_in[2];
    const float* w1_rel  = (const float*)d_in[3];
    const float* w1_root = (const float*)d_in[4];
    const float* b1      = (const float*)d_in[5];
    const float* w_rel   = (const float*)d_in[6];   // [4,100,100]
    const float* w_root  = (const float*)d_in[7];   // [4,100,100]
    const float* bb      = (const float*)d_in[8];   // [4,100]
    const float* lw1     = (const float*)d_in[9];
    const float* lb1     = (const float*)d_in[10];
    const float* lw2     = (const float*)d_in[11];
    const float* lb2     = (const float*)d_in[12];
    const float* lw3     = (const float*)d_in[13];
    const float* lb3     = (const float*)d_in[14];
    float* out = (float*)d_out;

    const int* src = ei;
    const int* dst = ei + NEDGES;

    float *buf0, *buf1, *pool, *m1, *m2;
    cudaGetSymbolAddress((void**)&buf0, g_buf0);
    cudaGetSymbolAddress((void**)&buf1, g_buf1);
    cudaGetSymbolAddress((void**)&pool, g_pool);
    cudaGetSymbolAddress((void**)&m1,   g_m1);
    cudaGetSymbolAddress((void**)&m2,   g_m2);

    const int SMEM_GEMM = (8192 + 128) * 4;   // 33280 B
    cudaFuncSetAttribute(gemm_bf16,
                         cudaFuncAttributeMaxDynamicSharedMemorySize, SMEM_GEMM);

    dim3 gemm_grid(NBLK, 2);
    const int gat_blocks = (NNODES + 7) / 8;
    const dim3 packw_grid((2 * 16 * 32 * NCH1 + 255) / 256, 5);

    // Launch order puts the layer-1 GEMM at index 3 (the profiled slot).
    csr_zero<<<(NNODES + 255) / 256, 256>>>();                          // 0
    conv_a<<<NBLK * NCH1, 256>>>(x, K1, NCH1, 0);                       // 1
    pack_weights<<<packw_grid, 256>>>(w1_rel, w1_root, w_rel, w_root);  // 2
    gemm_bf16<<<gemm_grid, 256, SMEM_GEMM>>>(NCH1, 0, b1, buf0);        // 3
    csr_count<<<(NEDGES + 255) / 256, 256>>>(dst);                      // 4
    csr_scan_local<<<NSCAN, SCAN_B>>>();
    csr_scan_bsums<<<1, 128>>>();
    csr_scan_add<<<(NNODES + 255) / 256, 256>>>();
    csr_fill<<<(NEDGES + 255) / 256, 256>>>(src, dst);
    gather_add<<<gat_blocks, 256>>>(buf0);

    // Layers 2..5 (relu folded into conv_a)
    float* bufs[2] = { buf0, buf1 };
    for (int l = 0; l < 4; l++) {
        float* bin  = bufs[l & 1];
        float* bout = bufs[(l + 1) & 1];
        size_t woff = L1WOFF + (size_t)l * 2 * NCHL * CBLK;
        conv_a<<<NBLK * NCHL, 256>>>(bin, HID, NCHL, 1);
        gemm_bf16<<<gemm_grid, 256, SMEM_GEMM>>>(NCHL, woff, bb + l * HID, bout);
        gather_add<<<gat_blocks, 256>>>(bout);
    }
    // Final conv output (pre-relu) is in buf0.

    pool_kernel<<<NGRAPHS, 128>>>(buf0, batch, pool);
    mlp_kernel<<<NGRAPHS, 128>>>(pool, lw1, lb1, m1, HID, HID, 1);
    mlp_kernel<<<NGRAPHS, 128>>>(m1,   lw2, lb2, m2, HID, HID, 1);
    mlp_kernel<<<NGRAPHS, 128>>>(m2,   lw3, lb3, out, HID, NOUT, 0);
}